// round 1
// baseline (speedup 1.0000x reference)
#include <cuda_runtime.h>

// Shapes: B=4, H=16, S=1024, D=64 (fp32)
// inputs: q [B,H,S,D], k [B,H,S,D], v [B,H,S,D], add_attn [B,1,S,S], mask [B,1,1,S] int32
// output buffer: out [B,H,S,D] followed by attn [B,H,S,S]

#define BQ 32
#define TPB 256
#define SEQ 1024
#define DH 64

// smem layout (floats): sc[BQ*SEQ] | Qs[BQ*DH] | KVs[64*DH] | mflag[SEQ]
#define SMEM_FLOATS (BQ*SEQ + BQ*DH + 64*DH + SEQ)

__global__ __launch_bounds__(TPB, 1)
void attn_fused_kernel(const float* __restrict__ q,
                       const float* __restrict__ k,
                       const float* __restrict__ v,
                       const float* __restrict__ add_attn,
                       const int*   __restrict__ mask,
                       float* __restrict__ out,
                       float* __restrict__ attn)
{
    extern __shared__ float sm[];
    float* sc    = sm;                   // [BQ][SEQ] score/prob buffer
    float* Qs    = sc + BQ * SEQ;        // [BQ][DH]
    float* KVs   = Qs + BQ * DH;         // [64][DH] (K transposed / V row-major)
    float* mflag = KVs + 64 * DH;        // [SEQ] 1.0 = keep, 0.0 = masked

    const int bh  = blockIdx.y;          // 0..63
    const int b   = bh >> 4;
    const int q0  = blockIdx.x * BQ;
    const int tid = threadIdx.x;
    const int jp  = tid & 31;            // key/dim pair index 0..31
    const int qg  = tid >> 5;            // q-row group 0..7 (4 rows each)

    const float* qbase    = q + ((size_t)bh * SEQ + q0) * DH;
    const float* kbase    = k + (size_t)bh * SEQ * DH;
    const float* vbase    = v + (size_t)bh * SEQ * DH;
    const float* biasbase = add_attn + (size_t)b * SEQ * SEQ + (size_t)q0 * SEQ;

    // ---- load Q tile (float4, coalesced) + mask flags ----
    for (int idx = tid; idx < BQ * (DH / 4); idx += TPB) {
        int row = idx >> 4, c = idx & 15;
        reinterpret_cast<float4*>(Qs + row * DH)[c] =
            reinterpret_cast<const float4*>(qbase + (size_t)row * DH)[c];
    }
    for (int kk = tid; kk < SEQ; kk += TPB)
        mflag[kk] = mask[b * SEQ + kk] ? 1.0f : 0.0f;

    const float scale = 0.125f;  // 1/sqrt(64)

    // ================= Phase 1: scores = QK^T*scale + bias, masked =========
    for (int kt = 0; kt < SEQ / 64; ++kt) {
        __syncthreads();
        // load K tile transposed: KVs[d*64 + key]
        for (int idx = tid; idx < 64 * (DH / 4); idx += TPB) {
            int key = idx >> 4, c = idx & 15;
            float4 k4 = reinterpret_cast<const float4*>(
                kbase + (size_t)(kt * 64 + key) * DH)[c];
            KVs[(c * 4 + 0) * 64 + key] = k4.x;
            KVs[(c * 4 + 1) * 64 + key] = k4.y;
            KVs[(c * 4 + 2) * 64 + key] = k4.z;
            KVs[(c * 4 + 3) * 64 + key] = k4.w;
        }
        __syncthreads();

        float acc[4][2] = {};
        #pragma unroll 16
        for (int d = 0; d < DH; ++d) {
            float2 kk2 = *reinterpret_cast<const float2*>(KVs + d * 64 + 2 * jp);
            #pragma unroll
            for (int i = 0; i < 4; ++i) {
                float a = Qs[(qg * 4 + i) * DH + d];  // warp broadcast
                acc[i][0] = fmaf(a, kk2.x, acc[i][0]);
                acc[i][1] = fmaf(a, kk2.y, acc[i][1]);
            }
        }
        const int kg = kt * 64 + 2 * jp;
        const float f0 = mflag[kg], f1 = mflag[kg + 1];
        #pragma unroll
        for (int i = 0; i < 4; ++i) {
            int row = qg * 4 + i;
            float2 bias = *reinterpret_cast<const float2*>(
                biasbase + (size_t)row * SEQ + kg);
            sc[row * SEQ + kg]     = (f0 != 0.0f) ? fmaf(acc[i][0], scale, bias.x) : -1e9f;
            sc[row * SEQ + kg + 1] = (f1 != 0.0f) ? fmaf(acc[i][1], scale, bias.y) : -1e9f;
        }
    }
    __syncthreads();

    // ================= Phase 2: softmax + write attn ========================
    {
        float* attnbase = attn + ((size_t)bh * SEQ + q0) * SEQ;
        const int w = qg, lane = jp;   // warp w owns rows 4w..4w+3
        for (int i = 0; i < 4; ++i) {
            int row = w * 4 + i;
            float* srow = sc + row * SEQ;
            float m = -3.0e38f;
            for (int kk = lane; kk < SEQ; kk += 32) m = fmaxf(m, srow[kk]);
            #pragma unroll
            for (int o = 16; o; o >>= 1) m = fmaxf(m, __shfl_xor_sync(~0u, m, o));
            float l = 0.0f;
            for (int kk = lane; kk < SEQ; kk += 32) {
                float e = __expf(srow[kk] - m);
                srow[kk] = e;
                l += e;
            }
            #pragma unroll
            for (int o = 16; o; o >>= 1) l += __shfl_xor_sync(~0u, l, o);
            float inv = 1.0f / l;
            float* arow = attnbase + (size_t)row * SEQ;
            for (int kk = lane; kk < SEQ; kk += 32) {
                float p = srow[kk] * inv;
                srow[kk] = p;
                arow[kk] = p;   // coalesced attn store
            }
        }
    }

    // ================= Phase 3: out = P @ V =================================
    float oacc[4][2] = {};
    for (int kt = 0; kt < SEQ / 64; ++kt) {
        __syncthreads();   // also orders phase-2 sc writes before first read
        for (int idx = tid; idx < 64 * (DH / 4); idx += TPB) {
            int key = idx >> 4, c = idx & 15;
            reinterpret_cast<float4*>(KVs + key * DH)[c] =
                reinterpret_cast<const float4*>(
                    vbase + (size_t)(kt * 64 + key) * DH)[c];
        }
        __syncthreads();
        #pragma unroll 8
        for (int kk = 0; kk < 64; ++kk) {
            float2 vv = *reinterpret_cast<const float2*>(KVs + kk * DH + 2 * jp);
            #pragma unroll
            for (int i = 0; i < 4; ++i) {
                float p = sc[(qg * 4 + i) * SEQ + kt * 64 + kk];  // broadcast
                oacc[i][0] = fmaf(p, vv.x, oacc[i][0]);
                oacc[i][1] = fmaf(p, vv.y, oacc[i][1]);
            }
        }
    }
    float* obase = out + ((size_t)bh * SEQ + q0) * DH;
    #pragma unroll
    for (int i = 0; i < 4; ++i) {
        float2 o2 = make_float2(oacc[i][0], oacc[i][1]);
        *reinterpret_cast<float2*>(obase + (qg * 4 + i) * DH + 2 * jp) = o2;
    }
}

extern "C" void kernel_launch(void* const* d_in, const int* in_sizes, int n_in,
                              void* d_out, int out_size)
{
    (void)in_sizes; (void)n_in; (void)out_size;
    const float* q        = (const float*)d_in[0];
    const float* k        = (const float*)d_in[1];
    const float* v        = (const float*)d_in[2];
    const float* add_attn = (const float*)d_in[3];
    const int*   mask     = (const int*)d_in[4];

    float* out  = (float*)d_out;                      // [4,16,1024,64]
    float* attn = out + (size_t)4 * 16 * 1024 * 64;   // [4,16,1024,1024]

    const size_t smem = SMEM_FLOATS * sizeof(float);  // 159,744 B
    cudaFuncSetAttribute(attn_fused_kernel,
                         cudaFuncAttributeMaxDynamicSharedMemorySize, (int)smem);

    dim3 grid(SEQ / BQ, 4 * 16);   // (32, 64)
    attn_fused_kernel<<<grid, TPB, smem>>>(q, k, v, add_attn, mask, out, attn);
}

// round 2
// speedup vs baseline: 1.6921x; 1.6921x over previous
#include <cuda_runtime.h>

// B=4, H=16, S=1024, D=64 fp32
// out buffer: out [B,H,S,D] then attn [B,H,S,S]

#define BQ   32
#define TPB  512
#define SEQ  1024
#define DH   64
#define KTILE 256        // keys per smem tile
#define SKT  257         // padded stride for K^T tile (floats)

// smem (floats): sc[32*1024] | KVs[64*257 >= 256*64] | Qs/rbuf[32*64] | mflag[1024]
#define SC_F    (BQ*SEQ)
#define KV_F    (DH*SKT)
#define QS_F    (BQ*DH)
#define MF_F    (SEQ)
#define SMEM_FLOATS (SC_F + KV_F + QS_F + MF_F)

__global__ __launch_bounds__(TPB, 1)
void attn_fused_kernel(const float* __restrict__ q,
                       const float* __restrict__ k,
                       const float* __restrict__ v,
                       const float* __restrict__ add_attn,
                       const int*   __restrict__ mask,
                       float* __restrict__ out,
                       float* __restrict__ attn)
{
    extern __shared__ float sm[];
    float* sc    = sm;                 // [32][1024]
    float* KVs   = sc + SC_F;          // K^T: [64][257] | V: [256][64]
    float* Qs    = KVs + KV_F;         // [32][64], reused as reduction buf
    float* mflag = Qs + QS_F;          // [1024]

    const int bh  = blockIdx.y;
    const int b   = bh >> 4;
    const int q0  = blockIdx.x * BQ;
    const int tid = threadIdx.x;
    const int jp  = tid & 31;
    const int wid = tid >> 5;          // 0..15
    const int qg  = wid & 7;           // row group (4 rows)
    const int kh  = wid >> 3;          // key half (128 keys)

    const float* qbase    = q + ((size_t)bh * SEQ + q0) * DH;
    const float* kbase    = k + (size_t)bh * SEQ * DH;
    const float* vbase    = v + (size_t)bh * SEQ * DH;
    const float* biasbase = add_attn + (size_t)b * SEQ * SEQ + (size_t)q0 * SEQ;

    // ---- load Q tile + mask flags ----
    for (int idx = tid; idx < BQ * (DH / 4); idx += TPB) {
        int row = idx >> 4, c = idx & 15;
        reinterpret_cast<float4*>(Qs + row * DH)[c] =
            reinterpret_cast<const float4*>(qbase + (size_t)row * DH)[c];
    }
    for (int kk = tid; kk < SEQ; kk += TPB)
        mflag[kk] = mask[b * SEQ + kk] ? 1.0f : 0.0f;

    const float scale = 0.125f;

    // ============ Phase 1: scores = QK^T*scale + bias, masked ============
    const int kb = kh * 128 + jp;   // lane's base key within tile (+32m)
    for (int kt = 0; kt < SEQ / KTILE; ++kt) {
        __syncthreads();
        // K tile -> KVs transposed [d][key], stride 257 (2-way STS, CF LDS)
        for (int idx = tid; idx < KTILE * (DH / 4); idx += TPB) {
            int key = idx >> 4, c = idx & 15;
            float4 k4 = reinterpret_cast<const float4*>(
                kbase + (size_t)(kt * KTILE + key) * DH)[c];
            KVs[(4 * c + 0) * SKT + key] = k4.x;
            KVs[(4 * c + 1) * SKT + key] = k4.y;
            KVs[(4 * c + 2) * SKT + key] = k4.z;
            KVs[(4 * c + 3) * SKT + key] = k4.w;
        }
        __syncthreads();

        float acc[4][4] = {};
        #pragma unroll
        for (int dt = 0; dt < 8; ++dt) {
            // Q for 4 rows x 8 d via float4 broadcasts
            float qr[4][8];
            #pragma unroll
            for (int i = 0; i < 4; ++i) {
                float4 a = *reinterpret_cast<const float4*>(
                    Qs + (qg * 4 + i) * DH + dt * 8);
                float4 bq = *reinterpret_cast<const float4*>(
                    Qs + (qg * 4 + i) * DH + dt * 8 + 4);
                qr[i][0]=a.x; qr[i][1]=a.y; qr[i][2]=a.z; qr[i][3]=a.w;
                qr[i][4]=bq.x; qr[i][5]=bq.y; qr[i][6]=bq.z; qr[i][7]=bq.w;
            }
            #pragma unroll
            for (int dd = 0; dd < 8; ++dd) {
                const float* kp = KVs + (dt * 8 + dd) * SKT + kb;
                float k0 = kp[0], k1 = kp[32], k2 = kp[64], k3 = kp[96];
                #pragma unroll
                for (int i = 0; i < 4; ++i) {
                    float a = qr[i][dd];
                    acc[i][0] = fmaf(a, k0, acc[i][0]);
                    acc[i][1] = fmaf(a, k1, acc[i][1]);
                    acc[i][2] = fmaf(a, k2, acc[i][2]);
                    acc[i][3] = fmaf(a, k3, acc[i][3]);
                }
            }
        }
        // epilogue: scale + bias + mask -> sc
        #pragma unroll
        for (int i = 0; i < 4; ++i) {
            int row = qg * 4 + i;
            const float* brow = biasbase + (size_t)row * SEQ;
            float* srow = sc + row * SEQ;
            #pragma unroll
            for (int m = 0; m < 4; ++m) {
                int kg = kt * KTILE + kb + 32 * m;
                float f = mflag[kg];
                srow[kg] = (f != 0.0f) ? fmaf(acc[i][m], scale, brow[kg])
                                       : -1e9f;
            }
        }
    }
    __syncthreads();

    // ============ Phase 2: softmax + write attn (2 rows per warp) ========
    {
        float* attnbase = attn + ((size_t)bh * SEQ + q0) * SEQ;
        #pragma unroll
        for (int i = 0; i < 2; ++i) {
            int row = wid * 2 + i;
            float* srow = sc + row * SEQ;
            float m = -3.0e38f;
            for (int kk = jp; kk < SEQ; kk += 32) m = fmaxf(m, srow[kk]);
            #pragma unroll
            for (int o = 16; o; o >>= 1) m = fmaxf(m, __shfl_xor_sync(~0u, m, o));
            float l = 0.0f;
            for (int kk = jp; kk < SEQ; kk += 32) {
                float e = __expf(srow[kk] - m);
                srow[kk] = e;
                l += e;
            }
            #pragma unroll
            for (int o = 16; o; o >>= 1) l += __shfl_xor_sync(~0u, l, o);
            float inv = 1.0f / l;
            float* arow = attnbase + (size_t)row * SEQ;
            for (int kk = jp; kk < SEQ; kk += 32) {
                float p = srow[kk] * inv;
                srow[kk] = p;
                arow[kk] = p;
            }
        }
    }

    // ============ Phase 3: out = P @ V (key-split across warp halves) ====
    float oacc[4][2] = {};
    for (int vt = 0; vt < SEQ / KTILE; ++vt) {
        __syncthreads();
        // V tile row-major [key][64], float2 stores (2-way), float2 loads CF
        for (int idx = tid; idx < KTILE * (DH / 2); idx += TPB) {
            int key = idx >> 5, c = idx & 31;
            *reinterpret_cast<float2*>(KVs + key * DH + 2 * c) =
                *reinterpret_cast<const float2*>(
                    vbase + (size_t)(vt * KTILE + key) * DH + 2 * c);
        }
        __syncthreads();

        const int klocal = kh * 128;   // this warp-half's 128 keys in tile
        #pragma unroll 4
        for (int t8 = 0; t8 < 16; ++t8) {
            int kk0 = klocal + t8 * 8;
            // preload P[4 rows][8 keys] via float4 broadcasts
            float pr[4][8];
            #pragma unroll
            for (int i = 0; i < 4; ++i) {
                const float* srow = sc + (qg * 4 + i) * SEQ + vt * KTILE + kk0;
                float4 p0 = *reinterpret_cast<const float4*>(srow);
                float4 p1 = *reinterpret_cast<const float4*>(srow + 4);
                pr[i][0]=p0.x; pr[i][1]=p0.y; pr[i][2]=p0.z; pr[i][3]=p0.w;
                pr[i][4]=p1.x; pr[i][5]=p1.y; pr[i][6]=p1.z; pr[i][7]=p1.w;
            }
            #pragma unroll
            for (int kk = 0; kk < 8; ++kk) {
                float2 vv = *reinterpret_cast<const float2*>(
                    KVs + (kk0 + kk) * DH + 2 * jp);
                #pragma unroll
                for (int i = 0; i < 4; ++i) {
                    oacc[i][0] = fmaf(pr[i][kk], vv.x, oacc[i][0]);
                    oacc[i][1] = fmaf(pr[i][kk], vv.y, oacc[i][1]);
                }
            }
        }
    }
    // cross-half reduction via Qs (free now)
    float* rbuf = Qs;
    if (kh == 1) {
        #pragma unroll
        for (int i = 0; i < 4; ++i)
            *reinterpret_cast<float2*>(rbuf + (qg * 4 + i) * DH + 2 * jp) =
                make_float2(oacc[i][0], oacc[i][1]);
    }
    __syncthreads();
    if (kh == 0) {
        float* obase = out + ((size_t)bh * SEQ + q0) * DH;
        #pragma unroll
        for (int i = 0; i < 4; ++i) {
            float2 r = *reinterpret_cast<const float2*>(
                rbuf + (qg * 4 + i) * DH + 2 * jp);
            *reinterpret_cast<float2*>(obase + (qg * 4 + i) * DH + 2 * jp) =
                make_float2(oacc[i][0] + r.x, oacc[i][1] + r.y);
        }
    }
}

extern "C" void kernel_launch(void* const* d_in, const int* in_sizes, int n_in,
                              void* d_out, int out_size)
{
    (void)in_sizes; (void)n_in; (void)out_size;
    const float* q        = (const float*)d_in[0];
    const float* k        = (const float*)d_in[1];
    const float* v        = (const float*)d_in[2];
    const float* add_attn = (const float*)d_in[3];
    const int*   mask     = (const int*)d_in[4];

    float* out  = (float*)d_out;
    float* attn = out + (size_t)4 * 16 * 1024 * 64;

    const size_t smem = SMEM_FLOATS * sizeof(float);  // ~204 KB
    cudaFuncSetAttribute(attn_fused_kernel,
                         cudaFuncAttributeMaxDynamicSharedMemorySize, (int)smem);

    dim3 grid(SEQ / BQ, 4 * 16);
    attn_fused_kernel<<<grid, TPB, smem>>>(q, k, v, add_attn, mask, out, attn);
}

// round 4
// speedup vs baseline: 2.5992x; 1.5361x over previous
#include <cuda_runtime.h>
#include <cuda_bf16.h>
#include <cstdint>

// B=4, H=16, S=1024, D=64 fp32. out buffer: out [B,H,S,D] then attn [B,H,S,S]
#define SEQ 1024
#define DH  64
#define BM  128
#define TPB 256
#define NCHUNK 8

// smem word offsets (uint32 words)
#define QF_W   0        // Qfrag  [2][8mt][4ks][32][4]  = 8192 w
#define PF_W   8192     // Pfrag  [2][8mt][8ks][32][4]  = 16384 w
#define KVF_W  24576    // Kfrag [2][16nt][4ks][32][2] / Vfrag [2][8nt][8ks][32][2] = 8192 w
#define MFL_W  32768    // mask flags [1024]
#define RED_W  33792    // [2][128]
#define RSUM_W 34048    // [128]
#define SM_WORDS 34176
#define SM_BYTES (SM_WORDS * 4)

__device__ __forceinline__ uint32_t bpack(float lo, float hi) {
    uint32_t u;
    asm("cvt.rn.bf16x2.f32 %0, %1, %2;" : "=r"(u) : "f"(hi), "f"(lo));
    return u;
}
__device__ __forceinline__ float bhi(float x) {
    return __bfloat162float(__float2bfloat16(x));
}
__device__ __forceinline__ void mma_bf16(float* d, uint32_t a0, uint32_t a1,
                                         uint32_t a2, uint32_t a3,
                                         uint32_t b0, uint32_t b1) {
    asm volatile(
        "mma.sync.aligned.m16n8k16.row.col.f32.bf16.bf16.f32 "
        "{%0,%1,%2,%3},{%4,%5,%6,%7},{%8,%9},{%0,%1,%2,%3};"
        : "+f"(d[0]), "+f"(d[1]), "+f"(d[2]), "+f"(d[3])
        : "r"(a0), "r"(a1), "r"(a2), "r"(a3), "r"(b0), "r"(b1));
}

__global__ __launch_bounds__(TPB, 1)
void attn_mma_kernel(const float* __restrict__ q,
                     const float* __restrict__ k,
                     const float* __restrict__ v,
                     const float* __restrict__ add_attn,
                     const int*   __restrict__ mask,
                     float* __restrict__ out,
                     float* __restrict__ attn)
{
    extern __shared__ uint32_t smw[];
    float* smf = reinterpret_cast<float*>(smw);

    const int tid  = threadIdx.x;
    const int w    = tid >> 5;
    const int lane = tid & 31;
    const int g    = lane >> 2;     // group 0..7
    const int tig  = lane & 3;      // thread-in-group
    const int wm   = w & 3;         // QK: row quarter (32 rows)
    const int wn   = w >> 2;        // QK: key half (64 keys)
    const int bh   = blockIdx.y;
    const int b    = bh >> 4;
    const int q0   = blockIdx.x * BM;

    const float* qbase = q + ((size_t)bh * SEQ + q0) * DH;
    const float* kbase = k + (size_t)bh * SEQ * DH;
    const float* vbase = v + (size_t)bh * SEQ * DH;
    const float* bias0 = add_attn + (size_t)b * SEQ * SEQ + (size_t)q0 * SEQ;
    float* attn0 = attn + ((size_t)bh * SEQ + q0) * SEQ;

    // ---- stage mask flags ----
    for (int i = tid; i < SEQ; i += TPB)
        smf[MFL_W + i] = mask[b * SEQ + i] ? 1.0f : 0.0f;

    // ---- stage Q (scaled, split hi/lo bf16, A-fragment order) ----
    #pragma unroll
    for (int i = 0; i < 8; ++i) {
        int idx = i * TPB + tid;
        int row = idx >> 4, dg = idx & 15;
        float4 qv = *(const float4*)(qbase + (size_t)row * DH + dg * 4);
        qv.x *= 0.125f; qv.y *= 0.125f; qv.z *= 0.125f; qv.w *= 0.125f;
        float hx = bhi(qv.x), hy = bhi(qv.y), hz = bhi(qv.z), hw = bhi(qv.w);
        int mt = row >> 4, gq = row & 7, rh = (row >> 3) & 1;
        int ks = dg >> 2, c = (dg & 3) * 4;
        int reg = ((c & 8) ? 2 : 0) + rh;
        int lane0 = gq * 4 + ((c & 7) >> 1);
        uint32_t base0 = QF_W + (((0 * 8 + mt) * 4 + ks) * 32 + lane0) * 4 + reg;
        uint32_t base1 = base0 + 4;                 // lane0+1
        smw[base0] = bpack(hx, hy);
        smw[base1] = bpack(hz, hw);
        smw[base0 + 4096] = bpack(qv.x - hx, qv.y - hy);
        smw[base1 + 4096] = bpack(qv.z - hz, qv.w - hw);
    }

    float mrun[2][2] = { { -3.0e38f, -3.0e38f }, { -3.0e38f, -3.0e38f } };

    // ================= Phase 1: S = QK^T + bias, masked; raw s -> attn ======
    for (int ct = 0; ct < NCHUNK; ++ct) {
        __syncthreads();
        // stage K chunk into B-fragment order (k-dim = d)
        #pragma unroll
        for (int i = 0; i < 8; ++i) {
            int idx = i * TPB + tid;
            int key = idx >> 4, dg = idx & 15;
            float4 kv = *(const float4*)(kbase + (size_t)(ct * 128 + key) * DH + dg * 4);
            float hx = bhi(kv.x), hy = bhi(kv.y), hz = bhi(kv.z), hw = bhi(kv.w);
            int nt = key >> 3, gk = key & 7;
            int ks = dg >> 2, c = (dg & 3) * 4;
            int reg = (c & 8) ? 1 : 0;
            int lane0 = gk * 4 + ((c & 7) >> 1);
            uint32_t base0 = KVF_W + (((0 * 16 + nt) * 4 + ks) * 32 + lane0) * 2 + reg;
            uint32_t base1 = base0 + 2;
            smw[base0] = bpack(hx, hy);
            smw[base1] = bpack(hz, hw);
            smw[base0 + 4096] = bpack(kv.x - hx, kv.y - hy);
            smw[base1 + 4096] = bpack(kv.z - hz, kv.w - hw);
        }
        __syncthreads();

        float sacc[2][8][4];
        #pragma unroll
        for (int mt = 0; mt < 2; ++mt)
            #pragma unroll
            for (int nt = 0; nt < 8; ++nt)
                #pragma unroll
                for (int r2 = 0; r2 < 4; ++r2) sacc[mt][nt][r2] = 0.0f;

        #pragma unroll
        for (int ks = 0; ks < 4; ++ks) {
            uint4 ah[2], al[2];
            #pragma unroll
            for (int mt = 0; mt < 2; ++mt) {
                uint32_t ao = QF_W + ((((wm * 2 + mt)) * 4 + ks) * 32 + lane) * 4;
                ah[mt] = *(const uint4*)&smw[ao];
                al[mt] = *(const uint4*)&smw[ao + 4096];
            }
            #pragma unroll
            for (int nt = 0; nt < 8; ++nt) {
                uint32_t bo = KVF_W + (((wn * 8 + nt) * 4 + ks) * 32 + lane) * 2;
                uint2 bhh = *(const uint2*)&smw[bo];
                uint2 bll = *(const uint2*)&smw[bo + 4096];
                #pragma unroll
                for (int mt = 0; mt < 2; ++mt) {
                    mma_bf16(sacc[mt][nt], ah[mt].x, ah[mt].y, ah[mt].z, ah[mt].w, bhh.x, bhh.y);
                    mma_bf16(sacc[mt][nt], ah[mt].x, ah[mt].y, ah[mt].z, ah[mt].w, bll.x, bll.y);
                    mma_bf16(sacc[mt][nt], al[mt].x, al[mt].y, al[mt].z, al[mt].w, bhh.x, bhh.y);
                }
            }
        }

        // epilogue: + bias, mask, raw s -> attn, running max
        #pragma unroll
        for (int mt = 0; mt < 2; ++mt) {
            int r0 = wm * 32 + mt * 16 + g;
            #pragma unroll
            for (int nt = 0; nt < 8; ++nt) {
                int col = wn * 64 + nt * 8 + 2 * tig;
                int gc  = ct * 128 + col;
                float2 mf = *(const float2*)&smf[MFL_W + gc];
                float2 bv0 = *(const float2*)(bias0 + (size_t)r0 * SEQ + gc);
                float2 bv1 = *(const float2*)(bias0 + (size_t)(r0 + 8) * SEQ + gc);
                float s0 = (mf.x != 0.0f) ? sacc[mt][nt][0] + bv0.x : -1e9f;
                float s1 = (mf.y != 0.0f) ? sacc[mt][nt][1] + bv0.y : -1e9f;
                float s2 = (mf.x != 0.0f) ? sacc[mt][nt][2] + bv1.x : -1e9f;
                float s3 = (mf.y != 0.0f) ? sacc[mt][nt][3] + bv1.y : -1e9f;
                *(float2*)(attn0 + (size_t)r0 * SEQ + gc)       = make_float2(s0, s1);
                *(float2*)(attn0 + (size_t)(r0 + 8) * SEQ + gc) = make_float2(s2, s3);
                mrun[mt][0] = fmaxf(mrun[mt][0], fmaxf(s0, s1));
                mrun[mt][1] = fmaxf(mrun[mt][1], fmaxf(s2, s3));
            }
        }
    }

    // ---- row max reduction ----
    #pragma unroll
    for (int mt = 0; mt < 2; ++mt)
        #pragma unroll
        for (int h = 0; h < 2; ++h) {
            float m = mrun[mt][h];
            m = fmaxf(m, __shfl_xor_sync(~0u, m, 1));
            m = fmaxf(m, __shfl_xor_sync(~0u, m, 2));
            if (tig == 0)
                smf[RED_W + wn * 128 + wm * 32 + mt * 16 + g + 8 * h] = m;
        }
    __syncthreads();

    // ---- pass 2: sum of exp per row (reload s via L2) ----
    {
        int row = tid >> 1;
        float mrow = fmaxf(smf[RED_W + row], smf[RED_W + 128 + row]);
        const float* srow = attn0 + (size_t)row * SEQ + (tid & 1) * 512;
        float l = 0.0f;
        #pragma unroll 8
        for (int f = 0; f < 128; ++f) {
            float4 sv = *(const float4*)(srow + f * 4);
            l += __expf(sv.x - mrow) + __expf(sv.y - mrow)
               + __expf(sv.z - mrow) + __expf(sv.w - mrow);
        }
        l += __shfl_xor_sync(~0u, l, 1);
        if ((tid & 1) == 0) smf[RSUM_W + row] = l;
    }

    // ================= Phase 3: p -> attn; P,V frags; O = P @ V =============
    float oacc[8][4];
    #pragma unroll
    for (int nt = 0; nt < 8; ++nt)
        #pragma unroll
        for (int r2 = 0; r2 < 4; ++r2) oacc[nt][r2] = 0.0f;

    for (int ct = 0; ct < NCHUNK; ++ct) {
        __syncthreads();
        // stage V chunk into B-fragment order (k-dim = keys, n = d)
        #pragma unroll
        for (int i = 0; i < 4; ++i) {
            int task = i * TPB + tid;
            int dg = task & 15, kp = task >> 4;   // kp 0..63
            int key = 2 * kp;
            const float* vp = vbase + (size_t)(ct * 128 + key) * DH + dg * 4;
            float4 va = *(const float4*)(vp);
            float4 vb = *(const float4*)(vp + DH);
            float a4[4] = { va.x, va.y, va.z, va.w };
            float b4[4] = { vb.x, vb.y, vb.z, vb.w };
            int ks = key >> 4, kc = key & 15;
            int reg = (kc & 8) ? 1 : 0;
            int tg = (kc & 7) >> 1;
            #pragma unroll
            for (int j = 0; j < 4; ++j) {
                int d = dg * 4 + j;
                int nt = d >> 3, gd = d & 7;
                float ha = bhi(a4[j]), hb = bhi(b4[j]);
                uint32_t off = KVF_W + (((0 * 8 + nt) * 8 + ks) * 32 + gd * 4 + tg) * 2 + reg;
                smw[off] = bpack(ha, hb);
                smw[off + 4096] = bpack(a4[j] - ha, b4[j] - hb);
            }
        }
        // stage P: p = exp(s - m)/l -> attn (final) + Pfrag hi/lo
        {
            int row = tid >> 1;
            float mrow = fmaxf(smf[RED_W + row], smf[RED_W + 128 + row]);
            float linv = 1.0f / smf[RSUM_W + row];
            int mt = row >> 4, gp = row & 7, rh = (row >> 3) & 1;
            int kb = (tid & 1) * 64;
            float* arow = attn0 + (size_t)row * SEQ + ct * 128;
            #pragma unroll
            for (int f = 0; f < 16; ++f) {
                int k0 = kb + f * 4;
                float4 sv = *(const float4*)(arow + k0);
                float4 pv;
                pv.x = __expf(sv.x - mrow) * linv;
                pv.y = __expf(sv.y - mrow) * linv;
                pv.z = __expf(sv.z - mrow) * linv;
                pv.w = __expf(sv.w - mrow) * linv;
                *(float4*)(arow + k0) = pv;
                float hx = bhi(pv.x), hy = bhi(pv.y), hz = bhi(pv.z), hw = bhi(pv.w);
                int ks = k0 >> 4, c = k0 & 15;
                int reg = ((c & 8) ? 2 : 0) + rh;
                int lane0 = gp * 4 + ((c & 7) >> 1);
                uint32_t base0 = PF_W + (((0 * 8 + mt) * 8 + ks) * 32 + lane0) * 4 + reg;
                uint32_t base1 = base0 + 4;
                smw[base0] = bpack(hx, hy);
                smw[base1] = bpack(hz, hw);
                smw[base0 + 8192] = bpack(pv.x - hx, pv.y - hy);
                smw[base1 + 8192] = bpack(pv.z - hz, pv.w - hw);
            }
        }
        __syncthreads();

        // PV mma: warp w owns rows w*16..w*16+15, all 64 d-cols
        #pragma unroll
        for (int ks = 0; ks < 8; ++ks) {
            uint32_t ao = PF_W + (((w) * 8 + ks) * 32 + lane) * 4;
            uint4 ah = *(const uint4*)&smw[ao];
            uint4 al = *(const uint4*)&smw[ao + 8192];
            #pragma unroll
            for (int nt = 0; nt < 8; ++nt) {
                uint32_t bo = KVF_W + ((nt * 8 + ks) * 32 + lane) * 2;
                uint2 bhh = *(const uint2*)&smw[bo];
                uint2 bll = *(const uint2*)&smw[bo + 4096];
                mma_bf16(oacc[nt], ah.x, ah.y, ah.z, ah.w, bhh.x, bhh.y);
                mma_bf16(oacc[nt], ah.x, ah.y, ah.z, ah.w, bll.x, bll.y);
                mma_bf16(oacc[nt], al.x, al.y, al.z, al.w, bhh.x, bhh.y);
            }
        }
    }

    // ---- write O ----
    {
        int r0 = w * 16 + g;
        float* orow0 = out + ((size_t)bh * SEQ + q0 + r0) * DH;
        float* orow1 = orow0 + (size_t)8 * DH;
        #pragma unroll
        for (int nt = 0; nt < 8; ++nt) {
            int col = nt * 8 + 2 * tig;
            *(float2*)(orow0 + col) = make_float2(oacc[nt][0], oacc[nt][1]);
            *(float2*)(orow1 + col) = make_float2(oacc[nt][2], oacc[nt][3]);
        }
    }
}

extern "C" void kernel_launch(void* const* d_in, const int* in_sizes, int n_in,
                              void* d_out, int out_size)
{
    (void)in_sizes; (void)n_in; (void)out_size;
    const float* q        = (const float*)d_in[0];
    const float* k        = (const float*)d_in[1];
    const float* v        = (const float*)d_in[2];
    const float* add_attn = (const float*)d_in[3];
    const int*   mask     = (const int*)d_in[4];

    float* out  = (float*)d_out;
    float* attn = out + (size_t)4 * 16 * 1024 * 64;

    cudaFuncSetAttribute(attn_mma_kernel,
                         cudaFuncAttributeMaxDynamicSharedMemorySize, SM_BYTES);

    dim3 grid(SEQ / BM, 4 * 16);   // (8, 64)
    attn_mma_kernel<<<grid, TPB, SM_BYTES>>>(q, k, v, add_attn, mask, out, attn);
}

// round 5
// speedup vs baseline: 2.6088x; 1.0037x over previous
#include <cuda_runtime.h>
#include <cuda_bf16.h>
#include <cstdint>

// B=4, H=16, S=1024, D=64 fp32. out buffer: out [B,H,S,D] then attn [B,H,S,S]
#define SEQ 1024
#define DH  64
#define BM  128
#define TPB 512
#define NCHUNK 8

// smem word offsets
#define QF_W   0        // Q frags: hi [8mt][4ks][32][4] = 4096 w, lo +4096 (8192 w). Reused as obuf in O-reduce.
#define PF_W   8192     // P frags: hi [8mt][8ks][32][4] = 8192 w, lo +8192 (16384 w)
#define KVF_W  24576    // K frags [16nt][4ks][32][4] / V frags [8nt][8ks][32][4], hi/lo interleaved (8192 w)
#define MFL_W  32768    // mask flags [1024]
#define RED_W  33792    // per-wc (m,l): float2 [4][128] = 1024 w
#define RST_W  34816    // rowstat (m, 1/l): float2 [128] = 256 w
#define SM_WORDS 35072
#define SM_BYTES (SM_WORDS * 4)

__device__ __forceinline__ uint32_t bpack(float lo, float hi) {
    uint32_t u;
    asm("cvt.rn.bf16x2.f32 %0, %1, %2;" : "=r"(u) : "f"(hi), "f"(lo));
    return u;
}
__device__ __forceinline__ float bhi(float x) {
    return __bfloat162float(__float2bfloat16(x));
}
__device__ __forceinline__ void mma_bf16(float* d, uint32_t a0, uint32_t a1,
                                         uint32_t a2, uint32_t a3,
                                         uint32_t b0, uint32_t b1) {
    asm volatile(
        "mma.sync.aligned.m16n8k16.row.col.f32.bf16.bf16.f32 "
        "{%0,%1,%2,%3},{%4,%5,%6,%7},{%8,%9},{%0,%1,%2,%3};"
        : "+f"(d[0]), "+f"(d[1]), "+f"(d[2]), "+f"(d[3])
        : "r"(a0), "r"(a1), "r"(a2), "r"(a3), "r"(b0), "r"(b1));
}

__global__ __launch_bounds__(TPB, 1)
void attn_mma_kernel(const float* __restrict__ q,
                     const float* __restrict__ k,
                     const float* __restrict__ v,
                     const float* __restrict__ add_attn,
                     const int*   __restrict__ mask,
                     float* __restrict__ out,
                     float* __restrict__ attn)
{
    extern __shared__ uint32_t smw[];
    float* smf = reinterpret_cast<float*>(smw);

    const int tid  = threadIdx.x;
    const int w    = tid >> 5;
    const int lane = tid & 31;
    const int g    = lane >> 2;
    const int tig  = lane & 3;
    const int wr   = w >> 2;        // QK: row group (32 rows)
    const int wc   = w & 3;         // QK: col group (32 keys)
    const int bh   = blockIdx.y;
    const int b    = bh >> 4;
    const int q0   = blockIdx.x * BM;

    const float* qbase = q + ((size_t)bh * SEQ + q0) * DH;
    const float* kbase = k + (size_t)bh * SEQ * DH;
    const float* vbase = v + (size_t)bh * SEQ * DH;
    const float* bias0 = add_attn + (size_t)b * SEQ * SEQ + (size_t)q0 * SEQ;
    float* attn0 = attn + ((size_t)bh * SEQ + q0) * SEQ;

    // ---- mask flags ----
    for (int i = tid; i < SEQ; i += TPB)
        smf[MFL_W + i] = mask[b * SEQ + i] ? 1.0f : 0.0f;

    // ---- stage Q (scaled, hi/lo bf16, A-frag order) ----
    #pragma unroll
    for (int i = 0; i < 4; ++i) {
        int idx = i * TPB + tid;
        int row = idx >> 4, dg = idx & 15;
        float4 qv = *(const float4*)(qbase + (size_t)row * DH + dg * 4);
        qv.x *= 0.125f; qv.y *= 0.125f; qv.z *= 0.125f; qv.w *= 0.125f;
        float hx = bhi(qv.x), hy = bhi(qv.y), hz = bhi(qv.z), hw = bhi(qv.w);
        int mtg = row >> 4, gq = row & 7, rh = (row >> 3) & 1;
        int ks = dg >> 2, c = (dg & 3) * 4;
        int reg = rh + ((c & 8) ? 2 : 0);
        int lane0 = gq * 4 + ((c & 7) >> 1);
        uint32_t a0 = QF_W + (uint32_t)(((mtg * 4 + ks) * 32 + lane0) * 4 + reg);
        smw[a0]     = bpack(hx, hy);
        smw[a0 + 4] = bpack(hz, hw);
        smw[a0 + 4096]     = bpack(qv.x - hx, qv.y - hy);
        smw[a0 + 4 + 4096] = bpack(qv.z - hz, qv.w - hw);
    }

    float om[2][2], ol[2][2];
    #pragma unroll
    for (int i = 0; i < 2; ++i)
        #pragma unroll
        for (int h = 0; h < 2; ++h) { om[i][h] = -3.0e38f; ol[i][h] = 0.0f; }

    // ================= Phase 1: S = QK^T + bias, masked; s -> attn; online (m,l)
    for (int ct = 0; ct < NCHUNK; ++ct) {
        __syncthreads();
        // stage K chunk: B-frag order, hi/lo interleaved in uint4
        #pragma unroll
        for (int i = 0; i < 4; ++i) {
            int idx = i * TPB + tid;
            int key = idx >> 4, dg = idx & 15;
            float4 kv = *(const float4*)(kbase + (size_t)(ct * 128 + key) * DH + dg * 4);
            float hx = bhi(kv.x), hy = bhi(kv.y), hz = bhi(kv.z), hw = bhi(kv.w);
            int nt = key >> 3;
            int ks = dg >> 2, c = (dg & 3) * 4;
            int reg = (c & 8) ? 1 : 0;
            int lane0 = (key & 7) * 4 + ((c & 7) >> 1);
            uint32_t base = KVF_W + (uint32_t)(((nt * 4 + ks) * 32 + lane0) * 4);
            smw[base + reg]         = bpack(hx, hy);
            smw[base + 4 + reg]     = bpack(hz, hw);
            smw[base + 2 + reg]     = bpack(kv.x - hx, kv.y - hy);
            smw[base + 6 + reg]     = bpack(kv.z - hz, kv.w - hw);
        }
        __syncthreads();

        float sacc[2][4][4];
        #pragma unroll
        for (int mt = 0; mt < 2; ++mt)
            #pragma unroll
            for (int nt = 0; nt < 4; ++nt)
                #pragma unroll
                for (int r2 = 0; r2 < 4; ++r2) sacc[mt][nt][r2] = 0.0f;

        #pragma unroll
        for (int ks = 0; ks < 4; ++ks) {
            uint4 ah[2], al[2];
            #pragma unroll
            for (int mt = 0; mt < 2; ++mt) {
                uint32_t ao = QF_W + (uint32_t)((((wr * 2 + mt) * 4 + ks) * 32 + lane) * 4);
                ah[mt] = *(const uint4*)&smw[ao];
                al[mt] = *(const uint4*)&smw[ao + 4096];
            }
            #pragma unroll
            for (int nt = 0; nt < 4; ++nt) {
                uint32_t bo = KVF_W + (uint32_t)((((wc * 4 + nt) * 4 + ks) * 32 + lane) * 4);
                uint4 bb = *(const uint4*)&smw[bo];
                #pragma unroll
                for (int mt = 0; mt < 2; ++mt) {
                    mma_bf16(sacc[mt][nt], ah[mt].x, ah[mt].y, ah[mt].z, ah[mt].w, bb.x, bb.y);
                    mma_bf16(sacc[mt][nt], ah[mt].x, ah[mt].y, ah[mt].z, ah[mt].w, bb.z, bb.w);
                    mma_bf16(sacc[mt][nt], al[mt].x, al[mt].y, al[mt].z, al[mt].w, bb.x, bb.y);
                }
            }
        }

        // epilogue: bias, mask, store raw s, online (m,l)
        #pragma unroll
        for (int mt = 0; mt < 2; ++mt) {
            int r0 = wr * 32 + mt * 16 + g;
            float sh0[8], sh1[8];
            #pragma unroll
            for (int nt = 0; nt < 4; ++nt) {
                int gc = ct * 128 + wc * 32 + nt * 8 + 2 * tig;
                float2 mf = *(const float2*)&smf[MFL_W + gc];
                float2 bv0 = *(const float2*)(bias0 + (size_t)r0 * SEQ + gc);
                float2 bv1 = *(const float2*)(bias0 + (size_t)(r0 + 8) * SEQ + gc);
                float s0 = (mf.x != 0.0f) ? sacc[mt][nt][0] + bv0.x : -1e9f;
                float s1 = (mf.y != 0.0f) ? sacc[mt][nt][1] + bv0.y : -1e9f;
                float s2 = (mf.x != 0.0f) ? sacc[mt][nt][2] + bv1.x : -1e9f;
                float s3 = (mf.y != 0.0f) ? sacc[mt][nt][3] + bv1.y : -1e9f;
                *(float2*)(attn0 + (size_t)r0 * SEQ + gc)       = make_float2(s0, s1);
                *(float2*)(attn0 + (size_t)(r0 + 8) * SEQ + gc) = make_float2(s2, s3);
                sh0[2*nt] = s0; sh0[2*nt+1] = s1;
                sh1[2*nt] = s2; sh1[2*nt+1] = s3;
            }
            #pragma unroll
            for (int h = 0; h < 2; ++h) {
                float* sh = h ? sh1 : sh0;
                float mloc = sh[0];
                #pragma unroll
                for (int j = 1; j < 8; ++j) mloc = fmaxf(mloc, sh[j]);
                float mn = fmaxf(om[mt][h], mloc);
                float acc = 0.0f;
                #pragma unroll
                for (int j = 0; j < 8; ++j) acc += __expf(sh[j] - mn);
                ol[mt][h] = ol[mt][h] * __expf(om[mt][h] - mn) + acc;
                om[mt][h] = mn;
            }
        }
    }

    // ---- reduce (m,l): across tig lanes, then across wc groups ----
    #pragma unroll
    for (int mt = 0; mt < 2; ++mt)
        #pragma unroll
        for (int h = 0; h < 2; ++h) {
            float m = om[mt][h], l = ol[mt][h];
            #pragma unroll
            for (int o = 1; o <= 2; o <<= 1) {
                float mo = __shfl_xor_sync(~0u, m, o);
                float lo_ = __shfl_xor_sync(~0u, l, o);
                float mn = fmaxf(m, mo);
                l = l * __expf(m - mn) + lo_ * __expf(mo - mn);
                m = mn;
            }
            if (tig == 0) {
                int row = wr * 32 + mt * 16 + g + 8 * h;
                *(float2*)&smf[RED_W + (wc * 128 + row) * 2] = make_float2(m, l);
            }
        }
    __syncthreads();
    if (tid < 128) {
        float2 a = *(const float2*)&smf[RED_W + (0 * 128 + tid) * 2];
        #pragma unroll
        for (int c = 1; c < 4; ++c) {
            float2 bq = *(const float2*)&smf[RED_W + (c * 128 + tid) * 2];
            float mn = fmaxf(a.x, bq.x);
            a.y = a.y * __expf(a.x - mn) + bq.y * __expf(bq.x - mn);
            a.x = mn;
        }
        *(float2*)&smf[RST_W + tid * 2] = make_float2(a.x, 1.0f / a.y);
    }
    __syncthreads();

    // ================= Phase 3: p -> attn; P,V frags; O = P @ V (k-split) ====
    // warp mapping: rg = w>>2 (32 rows), dg = (w>>1)&1 (32 d-cols), kg = w&1 (64 keys)
    const int rg = w >> 2, dgr = (w >> 1) & 1, kg = w & 1;
    const int prow = tid >> 2, pq = tid & 3;
    const float2 rst = *(const float2*)&smf[RST_W + prow * 2];   // (m, 1/l)
    const int pmtg = prow >> 4, pg = prow & 7, prh = (prow >> 3) & 1;

    float oacc[2][4][4];
    #pragma unroll
    for (int mt = 0; mt < 2; ++mt)
        #pragma unroll
        for (int nt = 0; nt < 4; ++nt)
            #pragma unroll
            for (int r2 = 0; r2 < 4; ++r2) oacc[mt][nt][r2] = 0.0f;

    for (int ct = 0; ct < NCHUNK; ++ct) {
        __syncthreads();
        // stage V chunk (B-frag order, k-dim = keys, hi/lo interleaved)
        #pragma unroll
        for (int i = 0; i < 2; ++i) {
            int task = i * TPB + tid;
            int kp = task >> 4, dg = task & 15;
            int key = 2 * kp;
            const float* vp = vbase + (size_t)(ct * 128 + key) * DH + dg * 4;
            float4 va = *(const float4*)(vp);
            float4 vb = *(const float4*)(vp + DH);
            float a4[4] = { va.x, va.y, va.z, va.w };
            float b4[4] = { vb.x, vb.y, vb.z, vb.w };
            int ks = kp >> 3;
            int reg = (kp & 4) ? 1 : 0;
            int tg = kp & 3;
            #pragma unroll
            for (int j = 0; j < 4; ++j) {
                int d = dg * 4 + j;
                int nt = d >> 3;
                float ha = bhi(a4[j]), hb = bhi(b4[j]);
                uint32_t base = KVF_W + (uint32_t)((((nt * 8 + ks) * 32 + (d & 7) * 4 + tg)) * 4);
                smw[base + reg]     = bpack(ha, hb);
                smw[base + 2 + reg] = bpack(a4[j] - ha, b4[j] - hb);
            }
        }
        // stage P: p = exp(s-m)/l -> attn (final) + P frags
        {
            float* arow = attn0 + (size_t)prow * SEQ + ct * 128 + pq * 32;
            #pragma unroll
            for (int f = 0; f < 8; ++f) {
                int k0 = pq * 32 + f * 4;
                float4 sv = *(const float4*)(arow + f * 4);
                float4 pv;
                pv.x = __expf(sv.x - rst.x) * rst.y;
                pv.y = __expf(sv.y - rst.x) * rst.y;
                pv.z = __expf(sv.z - rst.x) * rst.y;
                pv.w = __expf(sv.w - rst.x) * rst.y;
                *(float4*)(arow + f * 4) = pv;
                float hx = bhi(pv.x), hy = bhi(pv.y), hz = bhi(pv.z), hw = bhi(pv.w);
                int ks = k0 >> 4, c = k0 & 15;
                int reg = prh + ((c & 8) ? 2 : 0);
                int lane0 = pg * 4 + ((c & 7) >> 1);
                uint32_t a0 = PF_W + (uint32_t)(((pmtg * 8 + ks) * 32 + lane0) * 4 + reg);
                smw[a0]     = bpack(hx, hy);
                smw[a0 + 4] = bpack(hz, hw);
                smw[a0 + 8192]     = bpack(pv.x - hx, pv.y - hy);
                smw[a0 + 4 + 8192] = bpack(pv.z - hz, pv.w - hw);
            }
        }
        __syncthreads();

        // PV mma: warp covers rows rg*32..+31, cols dgr*32..+31, keys kg*64..+63
        #pragma unroll
        for (int ksl = 0; ksl < 4; ++ksl) {
            int ks = kg * 4 + ksl;
            uint4 ah[2], al[2];
            #pragma unroll
            for (int mt = 0; mt < 2; ++mt) {
                uint32_t ao = PF_W + (uint32_t)((((rg * 2 + mt) * 8 + ks) * 32 + lane) * 4);
                ah[mt] = *(const uint4*)&smw[ao];
                al[mt] = *(const uint4*)&smw[ao + 8192];
            }
            #pragma unroll
            for (int nt = 0; nt < 4; ++nt) {
                uint32_t bo = KVF_W + (uint32_t)((((dgr * 4 + nt) * 8 + ks) * 32 + lane) * 4);
                uint4 bb = *(const uint4*)&smw[bo];
                #pragma unroll
                for (int mt = 0; mt < 2; ++mt) {
                    mma_bf16(oacc[mt][nt], ah[mt].x, ah[mt].y, ah[mt].z, ah[mt].w, bb.x, bb.y);
                    mma_bf16(oacc[mt][nt], ah[mt].x, ah[mt].y, ah[mt].z, ah[mt].w, bb.z, bb.w);
                    mma_bf16(oacc[mt][nt], al[mt].x, al[mt].y, al[mt].z, al[mt].w, bb.x, bb.y);
                }
            }
        }
    }

    // ---- O reduction across kg pairs via smem (reuse QF region as [128][64]) ----
    float* obuf = &smf[QF_W];
    __syncthreads();
    if (kg == 1) {
        #pragma unroll
        for (int mt = 0; mt < 2; ++mt) {
            int r0 = rg * 32 + mt * 16 + g;
            #pragma unroll
            for (int nt = 0; nt < 4; ++nt) {
                int col = dgr * 32 + nt * 8 + 2 * tig;
                *(float2*)&obuf[r0 * 64 + col]       = make_float2(oacc[mt][nt][0], oacc[mt][nt][1]);
                *(float2*)&obuf[(r0 + 8) * 64 + col] = make_float2(oacc[mt][nt][2], oacc[mt][nt][3]);
            }
        }
    }
    __syncthreads();
    if (kg == 0) {
        #pragma unroll
        for (int mt = 0; mt < 2; ++mt) {
            int r0 = rg * 32 + mt * 16 + g;
            float* orow0 = out + ((size_t)bh * SEQ + q0 + r0) * DH;
            float* orow1 = orow0 + (size_t)8 * DH;
            #pragma unroll
            for (int nt = 0; nt < 4; ++nt) {
                int col = dgr * 32 + nt * 8 + 2 * tig;
                float2 p0 = *(const float2*)&obuf[r0 * 64 + col];
                float2 p1 = *(const float2*)&obuf[(r0 + 8) * 64 + col];
                *(float2*)(orow0 + col) = make_float2(oacc[mt][nt][0] + p0.x,
                                                      oacc[mt][nt][1] + p0.y);
                *(float2*)(orow1 + col) = make_float2(oacc[mt][nt][2] + p1.x,
                                                      oacc[mt][nt][3] + p1.y);
            }
        }
    }
}

extern "C" void kernel_launch(void* const* d_in, const int* in_sizes, int n_in,
                              void* d_out, int out_size)
{
    (void)in_sizes; (void)n_in; (void)out_size;
    const float* q        = (const float*)d_in[0];
    const float* k        = (const float*)d_in[1];
    const float* v        = (const float*)d_in[2];
    const float* add_attn = (const float*)d_in[3];
    const int*   mask     = (const int*)d_in[4];

    float* out  = (float*)d_out;
    float* attn = out + (size_t)4 * 16 * 1024 * 64;

    cudaFuncSetAttribute(attn_mma_kernel,
                         cudaFuncAttributeMaxDynamicSharedMemorySize, SM_BYTES);

    dim3 grid(SEQ / BM, 4 * 16);   // (8, 64)
    attn_mma_kernel<<<grid, TPB, SM_BYTES>>>(q, k, v, add_attn, mask, out, attn);
}

// round 6
// speedup vs baseline: 3.9343x; 1.5081x over previous
#include <cuda_runtime.h>
#include <cuda_bf16.h>
#include <cstdint>

// B=4, H=16, S=1024, D=64 fp32. out buffer: out [B,H,S,D] then attn [B,H,S,S]
#define SEQ 1024
#define DH  64
#define BM  128
#define TPB 256
#define NCHUNK 8

// smem word offsets
#define KVF_W 0        // K frags [16nt][4ks][32][4] / V frags [8nt][8ks][32][4] = 8192 w
#define QL_W  8192     // Q lo frags [8w][4ks][32][4] = 4096 w
#define MFL_W 12288    // mask flags [1024]
#define SM_WORDS 13312
#define SM_BYTES (SM_WORDS * 4)

__device__ __forceinline__ uint32_t bpack(float lo, float hi) {
    uint32_t u;
    asm("cvt.rn.bf16x2.f32 %0, %1, %2;" : "=r"(u) : "f"(hi), "f"(lo));
    return u;
}
__device__ __forceinline__ float bhi(float x) {
    return __bfloat162float(__float2bfloat16(x));
}
__device__ __forceinline__ void mma_bf16(float* d, uint32_t a0, uint32_t a1,
                                         uint32_t a2, uint32_t a3,
                                         uint32_t b0, uint32_t b1) {
    asm volatile(
        "mma.sync.aligned.m16n8k16.row.col.f32.bf16.bf16.f32 "
        "{%0,%1,%2,%3},{%4,%5,%6,%7},{%8,%9},{%0,%1,%2,%3};"
        : "+f"(d[0]), "+f"(d[1]), "+f"(d[2]), "+f"(d[3])
        : "r"(a0), "r"(a1), "r"(a2), "r"(a3), "r"(b0), "r"(b1));
}

__global__ __launch_bounds__(TPB, 2)
void attn_flash_kernel(const float* __restrict__ q,
                       const float* __restrict__ k,
                       const float* __restrict__ v,
                       const float* __restrict__ add_attn,
                       const int*   __restrict__ mask,
                       float* __restrict__ out,
                       float* __restrict__ attn)
{
    extern __shared__ uint32_t smw[];
    float* smf = reinterpret_cast<float*>(smw);

    const int tid  = threadIdx.x;
    const int w    = tid >> 5;
    const int lane = tid & 31;
    const int g    = lane >> 2;
    const int tig  = lane & 3;
    const int bh   = blockIdx.y;
    const int b    = bh >> 4;
    const int q0   = blockIdx.x * BM;
    const int r0   = w * 16;             // warp's 16 rows

    const float* qbase = q + ((size_t)bh * SEQ + q0) * DH;
    const float* kbase = k + (size_t)bh * SEQ * DH;
    const float* vbase = v + (size_t)bh * SEQ * DH;
    const float* bias0 = add_attn + (size_t)b * SEQ * SEQ + (size_t)q0 * SEQ;
    float* attn0 = attn + ((size_t)bh * SEQ + q0) * SEQ;

    // ---- mask flags ----
    for (int i = tid; i < SEQ; i += TPB)
        smf[MFL_W + i] = mask[b * SEQ + i] ? 1.0f : 0.0f;

    // ---- Q A-fragments: hi in regs, lo in private smem slice ----
    uint4 qh[4];
    {
        const float* qr0 = qbase + (size_t)(r0 + g) * DH;
        const float* qr1 = qr0 + (size_t)8 * DH;
        #pragma unroll
        for (int ks = 0; ks < 4; ++ks) {
            float2 x0 = *(const float2*)(qr0 + ks * 16 + 2 * tig);
            float2 x1 = *(const float2*)(qr1 + ks * 16 + 2 * tig);
            float2 x2 = *(const float2*)(qr0 + ks * 16 + 2 * tig + 8);
            float2 x3 = *(const float2*)(qr1 + ks * 16 + 2 * tig + 8);
            x0.x *= 0.125f; x0.y *= 0.125f; x1.x *= 0.125f; x1.y *= 0.125f;
            x2.x *= 0.125f; x2.y *= 0.125f; x3.x *= 0.125f; x3.y *= 0.125f;
            float h0x = bhi(x0.x), h0y = bhi(x0.y), h1x = bhi(x1.x), h1y = bhi(x1.y);
            float h2x = bhi(x2.x), h2y = bhi(x2.y), h3x = bhi(x3.x), h3y = bhi(x3.y);
            qh[ks].x = bpack(h0x, h0y);
            qh[ks].y = bpack(h1x, h1y);
            qh[ks].z = bpack(h2x, h2y);
            qh[ks].w = bpack(h3x, h3y);
            uint4 ql;
            ql.x = bpack(x0.x - h0x, x0.y - h0y);
            ql.y = bpack(x1.x - h1x, x1.y - h1y);
            ql.z = bpack(x2.x - h2x, x2.y - h2y);
            ql.w = bpack(x3.x - h3x, x3.y - h3y);
            *(uint4*)&smw[QL_W + (uint32_t)(((w * 4 + ks) * 32 + lane) * 4)] = ql;
        }
    }

    float om0 = -3.0e38f, ol0 = 0.0f, om1 = -3.0e38f, ol1 = 0.0f;

    // ================= Pass A: S = QK^T + bias, masked -> attn; online (m,l)
    for (int ct = 0; ct < NCHUNK; ++ct) {
        __syncthreads();
        // stage K chunk (B-frag order, hi/lo interleaved in uint4)
        #pragma unroll
        for (int i = 0; i < 8; ++i) {
            int idx = i * TPB + tid;
            int key = idx >> 4, dg = idx & 15;
            float4 kv = *(const float4*)(kbase + (size_t)(ct * 128 + key) * DH + dg * 4);
            float hx = bhi(kv.x), hy = bhi(kv.y), hz = bhi(kv.z), hw = bhi(kv.w);
            int nt = key >> 3;
            int ks = dg >> 2, c = (dg & 3) * 4;
            int reg = (c & 8) ? 1 : 0;
            int lane0 = (key & 7) * 4 + ((c & 7) >> 1);
            uint32_t base = KVF_W + (uint32_t)(((nt * 4 + ks) * 32 + lane0) * 4);
            smw[base + reg]     = bpack(hx, hy);
            smw[base + 4 + reg] = bpack(hz, hw);
            smw[base + 2 + reg] = bpack(kv.x - hx, kv.y - hy);
            smw[base + 6 + reg] = bpack(kv.z - hz, kv.w - hw);
        }
        __syncthreads();

        float sacc[16][4];
        #pragma unroll
        for (int nt = 0; nt < 16; ++nt)
            #pragma unroll
            for (int r2 = 0; r2 < 4; ++r2) sacc[nt][r2] = 0.0f;

        #pragma unroll
        for (int ks = 0; ks < 4; ++ks) {
            uint4 ql = *(const uint4*)&smw[QL_W + (uint32_t)(((w * 4 + ks) * 32 + lane) * 4)];
            #pragma unroll
            for (int nt = 0; nt < 16; ++nt) {
                uint4 bb = *(const uint4*)&smw[KVF_W + (uint32_t)(((nt * 4 + ks) * 32 + lane) * 4)];
                mma_bf16(sacc[nt], qh[ks].x, qh[ks].y, qh[ks].z, qh[ks].w, bb.x, bb.y);
                mma_bf16(sacc[nt], qh[ks].x, qh[ks].y, qh[ks].z, qh[ks].w, bb.z, bb.w);
                mma_bf16(sacc[nt], ql.x, ql.y, ql.z, ql.w, bb.x, bb.y);
            }
        }

        // epilogue: bias + mask, write raw s, chunk max
        float ml0 = -3.0e38f, ml1 = -3.0e38f;
        #pragma unroll
        for (int nt = 0; nt < 16; ++nt) {
            int gc = ct * 128 + nt * 8 + 2 * tig;
            float2 mf = *(const float2*)&smf[MFL_W + gc];
            float2 b0 = *(const float2*)(bias0 + (size_t)(r0 + g) * SEQ + gc);
            float2 b1 = *(const float2*)(bias0 + (size_t)(r0 + g + 8) * SEQ + gc);
            float s0 = (mf.x != 0.0f) ? sacc[nt][0] + b0.x : -1e9f;
            float s1 = (mf.y != 0.0f) ? sacc[nt][1] + b0.y : -1e9f;
            float s2 = (mf.x != 0.0f) ? sacc[nt][2] + b1.x : -1e9f;
            float s3 = (mf.y != 0.0f) ? sacc[nt][3] + b1.y : -1e9f;
            *(float2*)(attn0 + (size_t)(r0 + g) * SEQ + gc)     = make_float2(s0, s1);
            *(float2*)(attn0 + (size_t)(r0 + g + 8) * SEQ + gc) = make_float2(s2, s3);
            sacc[nt][0] = s0; sacc[nt][1] = s1; sacc[nt][2] = s2; sacc[nt][3] = s3;
            ml0 = fmaxf(ml0, fmaxf(s0, s1));
            ml1 = fmaxf(ml1, fmaxf(s2, s3));
        }
        float mn0 = fmaxf(om0, ml0), mn1 = fmaxf(om1, ml1);
        float a0 = 0.0f, a1 = 0.0f;
        #pragma unroll
        for (int nt = 0; nt < 16; ++nt) {
            a0 += __expf(sacc[nt][0] - mn0) + __expf(sacc[nt][1] - mn0);
            a1 += __expf(sacc[nt][2] - mn1) + __expf(sacc[nt][3] - mn1);
        }
        ol0 = ol0 * __expf(om0 - mn0) + a0;  om0 = mn0;
        ol1 = ol1 * __expf(om1 - mn1) + a1;  om1 = mn1;
    }

    // ---- finalize (m, 1/l) per row: reduce across tig lanes (all lanes get result)
    #pragma unroll
    for (int o = 1; o <= 2; o <<= 1) {
        float mo = __shfl_xor_sync(~0u, om0, o);
        float lo_ = __shfl_xor_sync(~0u, ol0, o);
        float mn = fmaxf(om0, mo);
        ol0 = ol0 * __expf(om0 - mn) + lo_ * __expf(mo - mn);
        om0 = mn;
        mo  = __shfl_xor_sync(~0u, om1, o);
        lo_ = __shfl_xor_sync(~0u, ol1, o);
        mn  = fmaxf(om1, mo);
        ol1 = ol1 * __expf(om1 - mn) + lo_ * __expf(mo - mn);
        om1 = mn;
    }
    const float rli0 = 1.0f / ol0;
    const float rli1 = 1.0f / ol1;

    // ================= Pass B: p = exp(s-m)/l -> attn; O = P @ V =============
    float oacc[8][4];
    #pragma unroll
    for (int nt = 0; nt < 8; ++nt)
        #pragma unroll
        for (int r2 = 0; r2 < 4; ++r2) oacc[nt][r2] = 0.0f;

    for (int ct = 0; ct < NCHUNK; ++ct) {
        __syncthreads();
        // stage V chunk (B-frag order, k-dim = keys, hi/lo interleaved)
        #pragma unroll
        for (int i = 0; i < 4; ++i) {
            int task = i * TPB + tid;
            int kp = task >> 4, dg = task & 15;
            int key = 2 * kp;
            const float* vp = vbase + (size_t)(ct * 128 + key) * DH + dg * 4;
            float4 va = *(const float4*)(vp);
            float4 vb = *(const float4*)(vp + DH);
            float a4[4] = { va.x, va.y, va.z, va.w };
            float b4[4] = { vb.x, vb.y, vb.z, vb.w };
            int ks = kp >> 3;
            int reg = (kp & 4) ? 1 : 0;
            int tg = kp & 3;
            #pragma unroll
            for (int j = 0; j < 4; ++j) {
                int d = dg * 4 + j;
                int nt = d >> 3;
                float ha = bhi(a4[j]), hb = bhi(b4[j]);
                uint32_t base = KVF_W + (uint32_t)(((nt * 8 + ks) * 32 + (d & 7) * 4 + tg) * 4);
                smw[base + reg]     = bpack(ha, hb);
                smw[base + 2 + reg] = bpack(a4[j] - ha, b4[j] - hb);
            }
        }
        __syncthreads();

        #pragma unroll
        for (int ks = 0; ks < 8; ++ks) {
            // read raw s for this warp's rows, k-window ks*16 (L2-resident)
            const float* ar0 = attn0 + (size_t)(r0 + g) * SEQ + ct * 128 + ks * 16;
            const float* ar1 = ar0 + (size_t)8 * SEQ;
            float2 s0 = *(const float2*)(ar0 + 2 * tig);
            float2 s1 = *(const float2*)(ar1 + 2 * tig);
            float2 s2 = *(const float2*)(ar0 + 2 * tig + 8);
            float2 s3 = *(const float2*)(ar1 + 2 * tig + 8);
            float2 p0, p1, p2, p3;
            p0.x = __expf(s0.x - om0) * rli0;  p0.y = __expf(s0.y - om0) * rli0;
            p1.x = __expf(s1.x - om1) * rli1;  p1.y = __expf(s1.y - om1) * rli1;
            p2.x = __expf(s2.x - om0) * rli0;  p2.y = __expf(s2.y - om0) * rli0;
            p3.x = __expf(s3.x - om1) * rli1;  p3.y = __expf(s3.y - om1) * rli1;
            *(float2*)(const_cast<float*>(ar0) + 2 * tig)     = p0;
            *(float2*)(const_cast<float*>(ar1) + 2 * tig)     = p1;
            *(float2*)(const_cast<float*>(ar0) + 2 * tig + 8) = p2;
            *(float2*)(const_cast<float*>(ar1) + 2 * tig + 8) = p3;
            // build P A-frags in regs
            float h0x = bhi(p0.x), h0y = bhi(p0.y), h1x = bhi(p1.x), h1y = bhi(p1.y);
            float h2x = bhi(p2.x), h2y = bhi(p2.y), h3x = bhi(p3.x), h3y = bhi(p3.y);
            uint32_t ah0 = bpack(h0x, h0y), ah1 = bpack(h1x, h1y);
            uint32_t ah2 = bpack(h2x, h2y), ah3 = bpack(h3x, h3y);
            uint32_t al0 = bpack(p0.x - h0x, p0.y - h0y);
            uint32_t al1 = bpack(p1.x - h1x, p1.y - h1y);
            uint32_t al2 = bpack(p2.x - h2x, p2.y - h2y);
            uint32_t al3 = bpack(p3.x - h3x, p3.y - h3y);
            #pragma unroll
            for (int nt = 0; nt < 8; ++nt) {
                uint4 bb = *(const uint4*)&smw[KVF_W + (uint32_t)(((nt * 8 + ks) * 32 + lane) * 4)];
                mma_bf16(oacc[nt], ah0, ah1, ah2, ah3, bb.x, bb.y);
                mma_bf16(oacc[nt], ah0, ah1, ah2, ah3, bb.z, bb.w);
                mma_bf16(oacc[nt], al0, al1, al2, al3, bb.x, bb.y);
            }
        }
    }

    // ---- write O directly (no cross-warp reduction needed) ----
    {
        float* orow0 = out + ((size_t)bh * SEQ + q0 + r0 + g) * DH;
        float* orow1 = orow0 + (size_t)8 * DH;
        #pragma unroll
        for (int nt = 0; nt < 8; ++nt) {
            int col = nt * 8 + 2 * tig;
            *(float2*)(orow0 + col) = make_float2(oacc[nt][0], oacc[nt][1]);
            *(float2*)(orow1 + col) = make_float2(oacc[nt][2], oacc[nt][3]);
        }
    }
}

extern "C" void kernel_launch(void* const* d_in, const int* in_sizes, int n_in,
                              void* d_out, int out_size)
{
    (void)in_sizes; (void)n_in; (void)out_size;
    const float* q        = (const float*)d_in[0];
    const float* k        = (const float*)d_in[1];
    const float* v        = (const float*)d_in[2];
    const float* add_attn = (const float*)d_in[3];
    const int*   mask     = (const int*)d_in[4];

    float* out  = (float*)d_out;
    float* attn = out + (size_t)4 * 16 * 1024 * 64;

    cudaFuncSetAttribute(attn_flash_kernel,
                         cudaFuncAttributeMaxDynamicSharedMemorySize, SM_BYTES);

    dim3 grid(SEQ / BM, 4 * 16);   // (8, 64)
    attn_flash_kernel<<<grid, TPB, SM_BYTES>>>(q, k, v, add_attn, mask, out, attn);
}